// round 15
// baseline (speedup 1.0000x reference)
#include <cuda_runtime.h>

#define NB    500            // DVH points per batch
#define NH    501            // histogram buckets (searchsorted index 0..500)
#define NHP   504            // padded row (int4-aligned: 504*4B = 2016B)
#define BATCH 4
#define NPER  (128*128*128)  // 2,097,152 elements per batch
#define NVEC  (NPER/4)       // float4 count per batch = 524288
#define GX    222            // x-blocks per batch -> 888 CTAs = 148 SMs x 6 (ONE wave)
#define TPB   256

// Persistent scratch (zero-init at module load; fin_k re-zeroes after use,
// so every graph replay sees clean state). Rows padded to 504 for int4 loads.
__device__ __align__(16) int g_hist[BATCH][NHP];  // diff histogram: pred - gt
__device__ int g_mcount[BATCH];                   // masked-voxel count per batch

__global__ __launch_bounds__(TPB, 6) void hist_k(
    const float* __restrict__ dpred,
    const float* __restrict__ dgt,
    const float* __restrict__ msk)
{
    __shared__ int sh[NH];
    const int tid = threadIdx.x;
    for (int i = tid; i < NH; i += TPB) sh[i] = 0;
    __syncthreads();

    const int b = blockIdx.y;
    const float4* __restrict__ p4 = (const float4*)(dpred + (size_t)b * NPER);
    const float4* __restrict__ g4 = (const float4*)(dgt   + (size_t)b * NPER);
    const float4* __restrict__ m4 = (const float4*)(msk   + (size_t)b * NPER);

    const float INVH = 499.0f / 75.0f;   // 1/h for bins = linspace(0,75,500)
    const int stride = GX * TPB;         // 56832
    int mc = 0;

    #pragma unroll 2
    for (int i = blockIdx.x * TPB + tid; i < NVEC; i += stride) {
        float4 m = __ldcs(&m4[i]);           // streaming: read-once data
        float4 a = __ldcs(&p4[i]);
        float4 g = __ldcs(&g4[i]);
        float mm[4] = {m.x, m.y, m.z, m.w};
        float aa[4] = {a.x, a.y, a.z, a.w};
        float gg[4] = {g.x, g.y, g.z, g.w};
        #pragma unroll
        for (int e = 0; e < 4; e++) {
            if (mm[e] != 0.0f) {               // mask is exactly 0.0 or 1.0
                mc++;
                int cp = min((int)(aa[e] * INVH) + 1, NB);
                int cg = min((int)(gg[e] * INVH) + 1, NB);
                atomicAdd(&sh[cp],  1);        // diff histogram: +pred
                atomicAdd(&sh[cg], -1);        //                 -gt
            }
        }
    }

    // masked count: warp reduce, one global RED per warp
    #pragma unroll
    for (int off = 16; off > 0; off >>= 1)
        mc += __shfl_down_sync(0xffffffffu, mc, off);
    if ((tid & 31) == 0 && mc) atomicAdd(&g_mcount[b], mc);

    __syncthreads();
    for (int i = tid; i < NH; i += TPB) {
        int v = sh[i];
        if (v) atomicAdd(&g_hist[b][i], v);    // RED, fire-and-forget
    }

    // PDL trigger at the VERY END (R13-measured optimum; early trigger
    // regressed 1.6us in R14). fin_k's ramp overlaps the CTA-drain tail;
    // cudaGridDependencySynchronize() in fin_k carries the dependency.
#if __CUDA_ARCH__ >= 900
    cudaTriggerProgrammaticLaunchCompletion();
#endif
}

// One warp per batch; int4-vectorized histogram read; register-resident
// suffix scan; re-zeroes scratch.
__global__ __launch_bounds__(128) void fin_k(float* __restrict__ out) {
    __shared__ float warp_acc[4];
    const int tid  = threadIdx.x;
    const int wid  = tid >> 5;
    const int lane = tid & 31;
    const unsigned FULL = 0xffffffffu;

#if __CUDA_ARCH__ >= 900
    cudaGridDependencySynchronize();   // wait for hist grid + visibility
#endif

    if (wid < BATCH) {
        const int b = wid;
        const float denom = (float)g_mcount[b] + 1e-6f;

        // Vector load: lane L holds hist[128*q + 4*L .. +3] for q=0..3
        // (4 int4 loads per lane instead of 16 scalar loads).
        const int4* __restrict__ h4 = (const int4*)&g_hist[b][0];
        float x[16];                    // x[4q+r] = hist[128q + 4*lane + r]
        #pragma unroll
        for (int q = 0; q < 4; q++) {
            int idx4 = q * 32 + lane;   // int4 index; 126 valid (NH=501 -> pad 0)
            int4 v = __ldcg(&h4[idx4]);
            int base = q * 128 + 4 * lane;
            x[4*q+0] = (base+0 < NH) ? (float)v.x : 0.0f;
            x[4*q+1] = (base+1 < NH) ? (float)v.y : 0.0f;
            x[4*q+2] = (base+2 < NH) ? (float)v.z : 0.0f;
            x[4*q+3] = (base+3 < NH) ? (float)v.w : 0.0f;
        }

        // Per-lane suffix within the 4-element group, per 128-block q:
        // then warp suffix-scan of group sums, then combine across q.
        float acc = 0.0f;
        float blk_tail = 0.0f;          // suffix of later q-blocks
        float blk_sum[4];
        float lane_suf[4][4];           // suffix value at element r within block q
        #pragma unroll
        for (int q = 3; q >= 0; q--) {
            // group suffix within lane's 4 elements
            float s3 = x[4*q+3];
            float s2 = x[4*q+2] + s3;
            float s1 = x[4*q+1] + s2;
            float s0 = x[4*q+0] + s1;
            // warp suffix-scan over group sums (s0 per lane)
            float g = s0;
            #pragma unroll
            for (int off = 1; off < 32; off <<= 1) {
                float t = __shfl_down_sync(FULL, g, off);
                if (lane + off < 32) g += t;
            }
            // suffix of groups strictly after this lane within block q
            float after = g - s0;
            lane_suf[q][0] = s0 + after;
            lane_suf[q][1] = s1 + after;
            lane_suf[q][2] = s2 + after;
            lane_suf[q][3] = s3 + after;
            blk_sum[q] = __shfl_sync(FULL, g, 0);   // total of block q
        }
        // block tails: suffix of blocks after q
        float tails[4];
        float run = 0.0f;
        #pragma unroll
        for (int q = 3; q >= 0; q--) { tails[q] = run; run += blk_sum[q]; }

        // loss over DVH points: suffix at histogram index 1..500
        #pragma unroll
        for (int q = 0; q < 4; q++) {
            #pragma unroll
            for (int r = 0; r < 4; r++) {
                int idx = q * 128 + 4 * lane + r;
                if (idx >= 1 && idx <= NB) {
                    float d = (lane_suf[q][r] + tails[q]) / denom;
                    acc += d * d;
                }
            }
        }
        #pragma unroll
        for (int off = 16; off > 0; off >>= 1)
            acc += __shfl_down_sync(FULL, acc, off);
        if (lane == 0) warp_acc[b] = acc;
    }
    __syncthreads();
    if (tid == 0)
        out[0] = (warp_acc[0] + warp_acc[1] + warp_acc[2] + warp_acc[3])
               / (float)(BATCH * NB);

    // self-clean for next replay (graph-capture safe, no extra kernel)
    for (int i = tid; i < BATCH * NHP; i += 128) ((int*)g_hist)[i] = 0;
    if (tid < BATCH) g_mcount[tid] = 0;
}

extern "C" void kernel_launch(void* const* d_in, const int* in_sizes, int n_in,
                              void* d_out, int out_size)
{
    const float* dpred = (const float*)d_in[0];
    const float* dgt   = (const float*)d_in[1];
    const float* msk   = (const float*)d_in[2];

    dim3 grid(GX, BATCH);            // 888 CTAs = exactly one full wave @ 6/SM
    hist_k<<<grid, TPB>>>(dpred, dgt, msk);

    // fin_k with Programmatic Stream Serialization (R13-proven config).
    cudaLaunchConfig_t cfg = {};
    cfg.gridDim  = dim3(1, 1, 1);
    cfg.blockDim = dim3(128, 1, 1);
    cfg.dynamicSmemBytes = 0;
    cfg.stream = 0;
    cudaLaunchAttribute attr[1];
    attr[0].id = cudaLaunchAttributeProgrammaticStreamSerialization;
    attr[0].val.programmaticStreamSerializationAllowed = 1;
    cfg.attrs = attr;
    cfg.numAttrs = 1;
    float* out = (float*)d_out;
    cudaError_t e = cudaLaunchKernelEx(&cfg, fin_k, out);
    if (e != cudaSuccess) {
        fin_k<<<1, 128>>>(out);   // fallback: plain dependent launch
    }
}

// round 16
// speedup vs baseline: 1.0321x; 1.0321x over previous
#include <cuda_runtime.h>

#define NB    500            // DVH points per batch
#define NH    501            // histogram buckets (searchsorted index 0..500)
#define BATCH 4
#define NPER  (128*128*128)  // 2,097,152 elements per batch
#define NVEC  (NPER/4)       // float4 count per batch = 524288
#define GX    222            // x-blocks per batch -> 888 CTAs = 148 SMs x 6 (ONE wave)
#define TPB   256

// Persistent scratch (zero-init at module load; fin_k re-zeroes after use,
// so every graph replay sees clean state).
__device__ int g_hist[BATCH][NH];   // difference histogram: pred - gt
__device__ int g_mcount[BATCH];     // masked-voxel count per batch

__global__ __launch_bounds__(TPB, 6) void hist_k(
    const float* __restrict__ dpred,
    const float* __restrict__ dgt,
    const float* __restrict__ msk)
{
    __shared__ int sh[NH];
    const int tid = threadIdx.x;
    for (int i = tid; i < NH; i += TPB) sh[i] = 0;
    __syncthreads();

    const int b = blockIdx.y;
    const float4* __restrict__ p4 = (const float4*)(dpred + (size_t)b * NPER);
    const float4* __restrict__ g4 = (const float4*)(dgt   + (size_t)b * NPER);
    const float4* __restrict__ m4 = (const float4*)(msk   + (size_t)b * NPER);

    const float INVH = 499.0f / 75.0f;   // 1/h for bins = linspace(0,75,500)
    const int stride = GX * TPB;         // 56832
    int mc = 0;

    #pragma unroll 2
    for (int i = blockIdx.x * TPB + tid; i < NVEC; i += stride) {
        float4 m = __ldcs(&m4[i]);           // streaming: read-once data
        float4 a = __ldcs(&p4[i]);
        float4 g = __ldcs(&g4[i]);
        float mm[4] = {m.x, m.y, m.z, m.w};
        float aa[4] = {a.x, a.y, a.z, a.w};
        float gg[4] = {g.x, g.y, g.z, g.w};
        #pragma unroll
        for (int e = 0; e < 4; e++) {
            if (mm[e] != 0.0f) {               // mask is exactly 0.0 or 1.0
                mc++;
                int cp = min((int)(aa[e] * INVH) + 1, NB);
                int cg = min((int)(gg[e] * INVH) + 1, NB);
                atomicAdd(&sh[cp],  1);        // diff histogram: +pred
                atomicAdd(&sh[cg], -1);        //                 -gt
            }
        }
    }

    // masked count: warp reduce, one global RED per warp
    #pragma unroll
    for (int off = 16; off > 0; off >>= 1)
        mc += __shfl_down_sync(0xffffffffu, mc, off);
    if ((tid & 31) == 0 && mc) atomicAdd(&g_mcount[b], mc);

    __syncthreads();
    for (int i = tid; i < NH; i += TPB) {
        int v = sh[i];
        if (v) atomicAdd(&g_hist[b][i], v);    // RED, fire-and-forget
    }

    // PDL: let the dependent fin_k begin its launch/ramp while remaining
    // hist CTAs drain. Trigger at the VERY END (measured optimum; early
    // trigger regressed 1.6us). Memory visibility for fin comes from its
    // cudaGridDependencySynchronize(), not from this trigger.
#if __CUDA_ARCH__ >= 900
    cudaTriggerProgrammaticLaunchCompletion();
#endif
}

// One warp per batch; register-resident suffix scan; re-zeroes scratch.
__global__ __launch_bounds__(128) void fin_k(float* __restrict__ out) {
    __shared__ float warp_acc[4];
    const int tid  = threadIdx.x;
    const int wid  = tid >> 5;
    const int lane = tid & 31;
    const unsigned FULL = 0xffffffffu;

#if __CUDA_ARCH__ >= 900
    cudaGridDependencySynchronize();   // wait for hist grid + visibility
#endif

    if (wid < BATCH) {
        const int b = wid;
        const float denom = (float)g_mcount[b] + 1e-6f;

        // 16 chunks of 32: register-resident inclusive suffix scan per chunk
        float s[16];
        #pragma unroll
        for (int k = 0; k < 16; k++) {
            int idx = k * 32 + lane;
            float v = (idx < NH) ? (float)g_hist[b][idx] : 0.0f;
            #pragma unroll
            for (int off = 1; off < 32; off <<= 1) {
                float t = __shfl_down_sync(FULL, v, off);
                if (lane + off < 32) v += t;
            }
            s[k] = v;
        }
        // chunk tails (suffix of chunk totals = lane-0 values)
        float tails[16];
        float run = 0.0f;
        #pragma unroll
        for (int k = 15; k >= 0; k--) {
            tails[k] = run;
            run += __shfl_sync(FULL, s[k], 0);
        }
        // loss over DVH points: suffix at histogram index 1..500
        float acc = 0.0f;
        #pragma unroll
        for (int k = 0; k < 16; k++) {
            int idx = k * 32 + lane;
            if (idx >= 1 && idx <= NB) {
                float d = (s[k] + tails[k]) / denom;
                acc += d * d;
            }
        }
        #pragma unroll
        for (int off = 16; off > 0; off >>= 1)
            acc += __shfl_down_sync(FULL, acc, off);
        if (lane == 0) warp_acc[b] = acc;
    }
    __syncthreads();
    if (tid == 0)
        out[0] = (warp_acc[0] + warp_acc[1] + warp_acc[2] + warp_acc[3])
               / (float)(BATCH * NB);

    // self-clean for next replay (graph-capture safe, no extra kernel)
    for (int i = tid; i < BATCH * NH; i += 128) ((int*)g_hist)[i] = 0;
    if (tid < BATCH) g_mcount[tid] = 0;
}

extern "C" void kernel_launch(void* const* d_in, const int* in_sizes, int n_in,
                              void* d_out, int out_size)
{
    const float* dpred = (const float*)d_in[0];
    const float* dgt   = (const float*)d_in[1];
    const float* msk   = (const float*)d_in[2];

    dim3 grid(GX, BATCH);            // 888 CTAs = exactly one full wave @ 6/SM
    hist_k<<<grid, TPB>>>(dpred, dgt, msk);

    // fin_k with Programmatic Stream Serialization; its launch/ramp overlaps
    // hist's tail. cudaGridDependencySynchronize() inside fin_k enforces the
    // data dependency.
    cudaLaunchConfig_t cfg = {};
    cfg.gridDim  = dim3(1, 1, 1);
    cfg.blockDim = dim3(128, 1, 1);
    cfg.dynamicSmemBytes = 0;
    cfg.stream = 0;
    cudaLaunchAttribute attr[1];
    attr[0].id = cudaLaunchAttributeProgrammaticStreamSerialization;
    attr[0].val.programmaticStreamSerializationAllowed = 1;
    cfg.attrs = attr;
    cfg.numAttrs = 1;
    float* out = (float*)d_out;
    cudaError_t e = cudaLaunchKernelEx(&cfg, fin_k, out);
    if (e != cudaSuccess) {
        fin_k<<<1, 128>>>(out);   // fallback: plain dependent launch
    }
}